// round 1
// baseline (speedup 1.0000x reference)
#include <cuda_runtime.h>
#include <cuda_bf16.h>

#define N_TOKENS   8192
#define N_EXPERTS  256
#define D_MODEL    4096
#define N_GROUP    4
#define GROUP_SIZE 64
#define TOPK_GROUP 2
#define ROUTED_SCALING 2.5f
#define EPS_ROUTE  1e-10f

// ---------------------------------------------------------------------------
// GEMM: logits[M,N] = A[M,K] * B[N,K]^T   (M=8192, N=256, K=4096), fp32.
// Tiles: BM=64, BN=64, BK=16. 16x16 threads, 4x4 microtile per thread.
// ---------------------------------------------------------------------------
__global__ __launch_bounds__(256) void moe_gate_gemm(
    const float* __restrict__ A,   // [M, K] hidden_states
    const float* __restrict__ B,   // [N, K] gate_w (torch Linear layout)
    float* __restrict__ C)         // [M, N] gate_logits
{
    __shared__ float As[16][64];
    __shared__ float Bs[16][64];

    const int tx = threadIdx.x;          // 0..15
    const int ty = threadIdx.y;          // 0..15
    const int tid = ty * 16 + tx;        // 0..255

    const int blockM = blockIdx.y * 64;
    const int blockN = blockIdx.x * 64;

    // Global-load assignment: each thread loads one float4 per tile per matrix.
    const int lrow = tid >> 2;           // 0..63  (tile row)
    const int lcol = (tid & 3) * 4;      // 0,4,8,12 (k offset within BK)

    const float* Aptr = A + (long)(blockM + lrow) * D_MODEL + lcol;
    const float* Bptr = B + (long)(blockN + lrow) * D_MODEL + lcol;

    float acc[4][4] = {};

    for (int k0 = 0; k0 < D_MODEL; k0 += 16) {
        float4 a4 = *(const float4*)(Aptr + k0);
        float4 b4 = *(const float4*)(Bptr + k0);

        As[lcol + 0][lrow] = a4.x;
        As[lcol + 1][lrow] = a4.y;
        As[lcol + 2][lrow] = a4.z;
        As[lcol + 3][lrow] = a4.w;
        Bs[lcol + 0][lrow] = b4.x;
        Bs[lcol + 1][lrow] = b4.y;
        Bs[lcol + 2][lrow] = b4.z;
        Bs[lcol + 3][lrow] = b4.w;

        __syncthreads();

        #pragma unroll
        for (int k = 0; k < 16; k++) {
            float4 av = *(const float4*)&As[k][ty * 4];
            float4 bv = *(const float4*)&Bs[k][tx * 4];
            float a[4] = {av.x, av.y, av.z, av.w};
            float b[4] = {bv.x, bv.y, bv.z, bv.w};
            #pragma unroll
            for (int i = 0; i < 4; i++)
                #pragma unroll
                for (int j = 0; j < 4; j++)
                    acc[i][j] = fmaf(a[i], b[j], acc[i][j]);
        }

        __syncthreads();
    }

    // Write 4x4 microtile.
    #pragma unroll
    for (int i = 0; i < 4; i++) {
        int row = blockM + ty * 4 + i;
        float4 v = make_float4(acc[i][0], acc[i][1], acc[i][2], acc[i][3]);
        *(float4*)&C[(long)row * N_EXPERTS + blockN + tx * 4] = v;
    }
}

// ---------------------------------------------------------------------------
// Epilogue: sigmoid -> group-limited top-2 (4 groups of 64) -> normalize.
// One block per token, 256 threads (one per expert).
// Tie-breaking matches jax.lax.top_k: strict '>' keeps the lowest index.
// ---------------------------------------------------------------------------
__global__ __launch_bounds__(256) void moe_gate_epilogue(
    const float* __restrict__ logits,   // [N_TOKENS, 256]
    float* __restrict__ out_idx,        // [N_TOKENS, 8] (indices as float)
    float* __restrict__ out_w)          // [N_TOKENS, 8]
{
    const int token = blockIdx.x;
    const int t = threadIdx.x;

    __shared__ float s[N_EXPERTS];
    __shared__ float w8[8];
    __shared__ int   i8[8];

    float x = logits[(long)token * N_EXPERTS + t];
    s[t] = 1.0f / (1.0f + __expf(-x));
    __syncthreads();

    if (t < N_GROUP) {
        const int base = t * GROUP_SIZE;
        float m1 = -1.0f, m2 = -1.0f;
        int   i1 = 0,     i2 = 0;
        #pragma unroll 8
        for (int j = 0; j < GROUP_SIZE; j++) {
            float v = s[base + j];
            if (v > m1) { m2 = m1; i2 = i1; m1 = v; i1 = j; }
            else if (v > m2) { m2 = v; i2 = j; }
        }
        w8[t * 2 + 0] = m1;  i8[t * 2 + 0] = base + i1;
        w8[t * 2 + 1] = m2;  i8[t * 2 + 1] = base + i2;
    }
    __syncthreads();

    if (t == 0) {
        float sum = 0.0f;
        #pragma unroll
        for (int j = 0; j < 8; j++) sum += w8[j];
        float scale = ROUTED_SCALING / (sum + EPS_ROUTE);
        #pragma unroll
        for (int j = 0; j < 8; j++) {
            out_idx[(long)token * 8 + j] = (float)i8[j];
            out_w[(long)token * 8 + j]   = w8[j] * scale;
        }
    }
}

// ---------------------------------------------------------------------------
// Launch
// ---------------------------------------------------------------------------
extern "C" void kernel_launch(void* const* d_in, const int* in_sizes, int n_in,
                              void* d_out, int out_size) {
    const float* hidden = (const float*)d_in[0];   // [8192, 4096]
    const float* gate_w = (const float*)d_in[1];   // [256, 4096]

    float* out = (float*)d_out;
    // Flattened tuple layout: topk_idx [8192,8], topk_weight [8192,8], gate_logits [8192,256]
    float* out_idx    = out;
    float* out_w      = out + (long)N_TOKENS * 8;
    float* out_logits = out + (long)N_TOKENS * 16;

    dim3 grid(N_EXPERTS / 64, N_TOKENS / 64);   // (4, 128)
    dim3 block(16, 16);
    moe_gate_gemm<<<grid, block>>>(hidden, gate_w, out_logits);

    moe_gate_epilogue<<<N_TOKENS, 256>>>(out_logits, out_idx, out_w);
}

// round 3
// speedup vs baseline: 2.6609x; 2.6609x over previous
#include <cuda_runtime.h>
#include <cuda_bf16.h>
#include <cstdint>

#define N_TOKENS   8192
#define N_EXPERTS  256
#define D_MODEL    4096
#define N_GROUP    4
#define GROUP_SIZE 64
#define ROUTED_SCALING 2.5f
#define EPS_ROUTE  1e-10f

// GEMM tiling
#define BM 128
#define BN 128
#define BK 32
#define CHUNKS (D_MODEL / BK)        // 128

// SMEM tile geometry (bf16 elements): 32 cols + 8 pad = 40 (80 B rows)
#define RS          40
#define TILE_ELEMS  (128 * RS)       // 5120 elems = 10240 B
#define STAGE_ELEMS (4 * TILE_ELEMS) // Ah, Al, Bh, Bl
#define STAGE_BYTES (STAGE_ELEMS * 2)
#define GEMM_SMEM   (2 * STAGE_BYTES) // 81920 B

// ---------------------------------------------------------------------------
// helpers
// ---------------------------------------------------------------------------
__device__ __forceinline__ uint32_t smem_u32(const void* p) {
    uint32_t a;
    asm("{ .reg .u64 t; cvta.to.shared.u64 t, %1; cvt.u32.u64 %0, t; }"
        : "=r"(a) : "l"(p));
    return a;
}

__device__ __forceinline__ void ldsm4(uint32_t& r0, uint32_t& r1,
                                      uint32_t& r2, uint32_t& r3, uint32_t addr) {
    asm volatile("ldmatrix.sync.aligned.m8n8.x4.shared.b16 {%0,%1,%2,%3}, [%4];"
                 : "=r"(r0), "=r"(r1), "=r"(r2), "=r"(r3) : "r"(addr));
}

__device__ __forceinline__ void mma16816(float* c, const uint32_t* a,
                                         uint32_t b0, uint32_t b1) {
    asm volatile(
        "mma.sync.aligned.m16n8k16.row.col.f32.bf16.bf16.f32 "
        "{%0,%1,%2,%3}, {%4,%5,%6,%7}, {%8,%9}, {%0,%1,%2,%3};"
        : "+f"(c[0]), "+f"(c[1]), "+f"(c[2]), "+f"(c[3])
        : "r"(a[0]), "r"(a[1]), "r"(a[2]), "r"(a[3]), "r"(b0), "r"(b1));
}

__device__ __forceinline__ uint32_t pack_bf16(__nv_bfloat16 a, __nv_bfloat16 b) {
    return (uint32_t)__bfloat16_as_ushort(a) |
           ((uint32_t)__bfloat16_as_ushort(b) << 16);
}

// ---------------------------------------------------------------------------
// GEMM: C[8192,256] = A[8192,4096] * B[256,4096]^T in fp32-accurate bf16x3.
// Per chunk: load fp32 tiles -> split to (hi,lo) bf16 in SMEM -> HMMA
//   C += Ah*Bh^T + Ah*Bl^T + Al*Bh^T  (fp32 accumulators, residual ~2^-17)
// ---------------------------------------------------------------------------
__global__ __launch_bounds__(256, 1) void gemm_bf16x3(
    const float* __restrict__ A,   // [M, K]
    const float* __restrict__ B,   // [N, K]
    float* __restrict__ C)         // [M, N]
{
    extern __shared__ __align__(128) __nv_bfloat16 smem[];
    const uint32_t sb = smem_u32(smem);

    const int tid = threadIdx.x;
    const int lid = tid & 31;
    const int wid = tid >> 5;
    const int warp_m = wid >> 2;       // 0..1 (64 rows each)
    const int warp_n = wid & 3;        // 0..3 (32 cols each)

    const int bm = blockIdx.y * BM;
    const int bn = blockIdx.x * BN;

    // global load coords: 4 float4 each for A and B per chunk
    const int gr = tid >> 3;           // 0..31 (row within 128, +32*i)
    const int gc = (tid & 7) * 4;      // col within 32

    float4 buf[8];
    float acc[4][4][4];
    #pragma unroll
    for (int i = 0; i < 4; i++)
        #pragma unroll
        for (int j = 0; j < 4; j++)
            #pragma unroll
            for (int k = 0; k < 4; k++) acc[i][j][k] = 0.0f;

    // ldmatrix source addresses (element offsets within a tile)
    const int a_row = warp_m * 64 + (lid & 15);      // + mt*16
    const int a_col = (lid >> 4) * 8;                // + ks*16
    const int b_row = warp_n * 32 + ((lid >> 4) << 3) + (lid & 7);  // + half*16
    const int b_col = ((lid >> 3) & 1) * 8;          // + ks*16

    auto load_chunk = [&](int c) {
        const int k0 = c * BK;
        #pragma unroll
        for (int i = 0; i < 4; i++) {
            buf[i]     = *(const float4*)(A + (size_t)(bm + gr + i * 32) * D_MODEL + k0 + gc);
            buf[i + 4] = *(const float4*)(B + (size_t)(bn + gr + i * 32) * D_MODEL + k0 + gc);
        }
    };

    auto store_chunk = [&](int s) {
        __nv_bfloat16* st = smem + s * STAGE_ELEMS;
        #pragma unroll
        for (int i = 0; i < 8; i++) {
            const int r = gr + (i & 3) * 32;
            float f[4] = {buf[i].x, buf[i].y, buf[i].z, buf[i].w};
            __nv_bfloat16 h[4], l[4];
            #pragma unroll
            for (int j = 0; j < 4; j++) {
                h[j] = __float2bfloat16_rn(f[j]);
                l[j] = __float2bfloat16_rn(f[j] - __bfloat162float(h[j]));
            }
            uint2 hv = make_uint2(pack_bf16(h[0], h[1]), pack_bf16(h[2], h[3]));
            uint2 lv = make_uint2(pack_bf16(l[0], l[1]), pack_bf16(l[2], l[3]));
            __nv_bfloat16* p = st + ((i < 4) ? 0 : 2 * TILE_ELEMS) + r * RS + gc;
            *(uint2*)p               = hv;
            *(uint2*)(p + TILE_ELEMS) = lv;
        }
    };

    auto compute = [&](int s) {
        const uint32_t st = sb + s * STAGE_BYTES;
        const uint32_t ah_base = st;
        const uint32_t al_base = st + TILE_ELEMS * 2;
        const uint32_t bh_base = st + 2 * TILE_ELEMS * 2;
        const uint32_t bl_base = st + 3 * TILE_ELEMS * 2;

        #pragma unroll
        for (int ks = 0; ks < 2; ks++) {
            // B fragments: two x4 loads cover 4 n8-tiles
            uint32_t bh[2][4], bl[2][4];
            #pragma unroll
            for (int half = 0; half < 2; half++) {
                uint32_t off = ((b_row + half * 16) * RS + b_col + ks * 16) * 2;
                ldsm4(bh[half][0], bh[half][1], bh[half][2], bh[half][3], bh_base + off);
                ldsm4(bl[half][0], bl[half][1], bl[half][2], bl[half][3], bl_base + off);
            }
            #pragma unroll
            for (int mt = 0; mt < 4; mt++) {
                uint32_t off = ((a_row + mt * 16) * RS + a_col + ks * 16) * 2;
                uint32_t ah[4], al[4];
                ldsm4(ah[0], ah[1], ah[2], ah[3], ah_base + off);
                ldsm4(al[0], al[1], al[2], al[3], al_base + off);
                #pragma unroll
                for (int nt = 0; nt < 4; nt++) {
                    uint32_t b0h = bh[nt >> 1][(nt & 1) * 2];
                    uint32_t b1h = bh[nt >> 1][(nt & 1) * 2 + 1];
                    uint32_t b0l = bl[nt >> 1][(nt & 1) * 2];
                    uint32_t b1l = bl[nt >> 1][(nt & 1) * 2 + 1];
                    mma16816(acc[mt][nt], ah, b0h, b1h);
                    mma16816(acc[mt][nt], ah, b0l, b1l);
                    mma16816(acc[mt][nt], al, b0h, b1h);
                }
            }
        }
    };

    load_chunk(0);
    store_chunk(0);
    __syncthreads();

    #pragma unroll 1
    for (int c = 0; c < CHUNKS; c++) {
        if (c + 1 < CHUNKS) load_chunk(c + 1);
        compute(c & 1);
        if (c + 1 < CHUNKS) store_chunk((c + 1) & 1);
        __syncthreads();
    }

    // writeback: each thread owns 2x2 floats per (mt, nt) tile
    #pragma unroll
    for (int mt = 0; mt < 4; mt++) {
        const int row0 = bm + warp_m * 64 + mt * 16 + (lid >> 2);
        #pragma unroll
        for (int nt = 0; nt < 4; nt++) {
            const int col = bn + warp_n * 32 + nt * 8 + (lid & 3) * 2;
            *(float2*)&C[(size_t)row0 * N_EXPERTS + col] =
                make_float2(acc[mt][nt][0], acc[mt][nt][1]);
            *(float2*)&C[(size_t)(row0 + 8) * N_EXPERTS + col] =
                make_float2(acc[mt][nt][2], acc[mt][nt][3]);
        }
    }
}

// ---------------------------------------------------------------------------
// Epilogue: sigmoid scores, group top-2 with exact-fp32 correction for
// near-tie groups, normalize, write idx/weights.
// ---------------------------------------------------------------------------
#define TIE_DELTA 2e-3f

__global__ __launch_bounds__(256) void moe_gate_epilogue(
    const float* __restrict__ logits,
    const float* __restrict__ hidden,
    const float* __restrict__ gate_w,
    float* __restrict__ out_idx,
    float* __restrict__ out_w)
{
    const int token = blockIdx.x;
    const int t = threadIdx.x;

    __shared__ float sc[N_EXPERTS];
    __shared__ float gv[N_GROUP][4];
    __shared__ int   gi[N_GROUP][4];
    __shared__ int   needg[N_GROUP];
    __shared__ float red[4][2];

    sc[t] = logits[(size_t)token * N_EXPERTS + t];
    __syncthreads();

    if (t < N_GROUP) {
        const int base = t * GROUP_SIZE;
        float v0 = -1e30f, v1 = -1e30f, v2 = -1e30f, v3 = -1e30f;
        int i0 = 0, i1 = 0, i2 = 0, i3 = 0;
        #pragma unroll 8
        for (int j = 0; j < GROUP_SIZE; j++) {
            float x = sc[base + j];
            if (x > v0)      { v3=v2; i3=i2; v2=v1; i2=i1; v1=v0; i1=i0; v0=x; i0=j; }
            else if (x > v1) { v3=v2; i3=i2; v2=v1; i2=i1; v1=x;  i1=j; }
            else if (x > v2) { v3=v2; i3=i2; v2=x;  i2=j; }
            else if (x > v3) { v3=x;  i3=j; }
        }
        gv[t][0]=v0; gv[t][1]=v1; gv[t][2]=v2; gv[t][3]=v3;
        gi[t][0]=base+i0; gi[t][1]=base+i1; gi[t][2]=base+i2; gi[t][3]=base+i3;
        needg[t] = ((v0 - v1) < TIE_DELTA) || ((v1 - v2) < TIE_DELTA) ? 1 : 0;
    }
    __syncthreads();

    for (int g = 0; g < N_GROUP; g++) {
        if (!needg[g]) continue;
        const int cand = t >> 6;
        const int j = t & 63;
        const int e = gi[g][cand];
        const float* wrow = gate_w + (size_t)e * D_MODEL;
        const float* hrow = hidden + (size_t)token * D_MODEL;
        float p = 0.0f;
        #pragma unroll 16
        for (int k = 0; k < D_MODEL / 64; k++)
            p = fmaf(hrow[j + k * 64], wrow[j + k * 64], p);
        #pragma unroll
        for (int off = 16; off; off >>= 1)
            p += __shfl_down_sync(0xffffffff, p, off);
        if ((t & 31) == 0) red[cand][(t >> 5) & 1] = p;
        __syncthreads();
        if (t < 4) gv[g][t] = red[t][0] + red[t][1];
        __syncthreads();
        if (t == 0) {
            #pragma unroll
            for (int a = 0; a < 3; a++) {
                int best = a;
                #pragma unroll
                for (int b = 1; b < 4; b++) {
                    if (b <= a) continue;
                    if (gv[g][b] > gv[g][best] ||
                        (gv[g][b] == gv[g][best] && gi[g][b] < gi[g][best]))
                        best = b;
                }
                float tv = gv[g][a]; gv[g][a] = gv[g][best]; gv[g][best] = tv;
                int ti = gi[g][a]; gi[g][a] = gi[g][best]; gi[g][best] = ti;
            }
        }
        __syncthreads();
    }

    if (t == 0) {
        float w8[8];
        int   i8[8];
        float sum = 0.0f;
        #pragma unroll
        for (int g = 0; g < N_GROUP; g++) {
            #pragma unroll
            for (int k = 0; k < 2; k++) {
                float s = 1.0f / (1.0f + __expf(-gv[g][k]));
                w8[g * 2 + k] = s;
                i8[g * 2 + k] = gi[g][k];
                sum += s;
            }
        }
        float scale = ROUTED_SCALING / (sum + EPS_ROUTE);
        #pragma unroll
        for (int j = 0; j < 8; j++) {
            out_idx[(size_t)token * 8 + j] = (float)i8[j];
            out_w[(size_t)token * 8 + j]   = w8[j] * scale;
        }
    }
}

// ---------------------------------------------------------------------------
// Launch
// ---------------------------------------------------------------------------
extern "C" void kernel_launch(void* const* d_in, const int* in_sizes, int n_in,
                              void* d_out, int out_size) {
    const float* hidden = (const float*)d_in[0];   // [8192, 4096]
    const float* gate_w = (const float*)d_in[1];   // [256, 4096]

    float* out = (float*)d_out;
    float* out_idx    = out;
    float* out_w      = out + (size_t)N_TOKENS * 8;
    float* out_logits = out + (size_t)N_TOKENS * 16;

    cudaFuncSetAttribute(gemm_bf16x3,
                         cudaFuncAttributeMaxDynamicSharedMemorySize, GEMM_SMEM);

    dim3 grid(N_EXPERTS / BN, N_TOKENS / BM);   // (2, 64)
    gemm_bf16x3<<<grid, 256, GEMM_SMEM>>>(hidden, gate_w, out_logits);

    moe_gate_epilogue<<<N_TOKENS, 256>>>(out_logits, hidden, gate_w,
                                         out_idx, out_w);
}